// round 16
// baseline (speedup 1.0000x reference)
#include <cuda_runtime.h>
#include <cuda_bf16.h>
#include <math.h>
#include <stdint.h>

#define NUM_J 23
#define NP 16
#define NT 192                 // vertices per CTA tile (8 warps x 3 n8-tiles x 8)
#define THREADS 256
#define W_STRIDE 24            // padded weights row (col 23 = 0)

// static smem layout (39936 B total, aliased across phases):
//   MMA phase:    [FRAG 18432][W 18432][V 3072]
//   setup phase:  sR@0 (17664) sG@17664 (17664) sSh@35328 (192)
//                 (frag emit overwrites dead sR; staging overwrites dead sG/sSh)
//   epilogue:     sE@0 (37120)
#define OFF_FRAG 0
#define OFF_W    18432
#define OFF_V    36864
#define SMEM_TOTAL 39936
#define POSE_STRIDE 580        // floats per pose in epilogue (192*3+4)

// ---------------- helpers ----------------
__device__ __forceinline__ uint32_t pk2(float lo, float hi) {
    __nv_bfloat162 t = __floats2bfloat162_rn(lo, hi);
    return *reinterpret_cast<uint32_t*>(&t);
}
__device__ __forceinline__ void split_bf(float v, float& h, float& l) {
    h = __bfloat162float(__float2bfloat16_rn(v));
    l = v - h;
}
__device__ __forceinline__ uint32_t prmt_hi(float a, float b) {   // {hi16(a), hi16(b)}
    uint32_t r;
    asm("prmt.b32 %0, %1, %2, 0x7632;" : "=r"(r)
        : "r"(__float_as_uint(a)), "r"(__float_as_uint(b)));
    return r;
}
__device__ __forceinline__ float trunc_hi(float a) {
    return __uint_as_float(__float_as_uint(a) & 0xffff0000u);
}
__device__ __forceinline__ void mma16816(float (&d)[4],
                                         uint32_t a0, uint32_t a1, uint32_t a2, uint32_t a3,
                                         uint32_t b0, uint32_t b1) {
    asm volatile("mma.sync.aligned.m16n8k16.row.col.f32.bf16.bf16.f32 "
                 "{%0,%1,%2,%3}, {%4,%5,%6,%7}, {%8,%9}, {%0,%1,%2,%3};"
                 : "+f"(d[0]), "+f"(d[1]), "+f"(d[2]), "+f"(d[3])
                 : "r"(a0), "r"(a1), "r"(a2), "r"(a3), "r"(b0), "r"(b1));
}

struct SetupArgs {
    const float* joints;
    const float* disp;
    const float* rnd;
    const float* prm[11];
    float* outJ;
};

__device__ const int   c_parents[NUM_J] = {-1,0,1,1,3,4,5,4,7,4,9,1,11,12,13,12,15,12,17,0,19,0,21};
__device__ const int   c_slot[NUM_J]    = { 0,-1,-1,1,2,3,-1,4,-1,5,-1,6,7,8,-1,9,-1,10,-1,-1,-1,-1,-1};
__device__ const float c_scale[11]      = {0.7853981633974483f, 1.5707963267948966f, 1.5707963267948966f,
                                           0.7853981633974483f, 0.7853981633974483f, 0.7853981633974483f,
                                           1.5707963267948966f, 1.5707963267948966f, 0.7853981633974483f,
                                           0.7853981633974483f, 0.7853981633974483f};

// ---------------------------------------------------------------------------
// Single fused kernel. Every CTA independently computes the pose setup
// (Rodrigues -> kinematic chain -> A affine with shift folded, valid since
// weight rows sum to 1) and its per-lane MMA A-fragments into smem, then runs
// its 192-vertex bf16 hi/lo tile GEMM. CTA 0 additionally writes the posed
// joints output. No cross-CTA communication at all.
// ---------------------------------------------------------------------------
__global__ __launch_bounds__(THREADS, 3) void lbs_one(const float* __restrict__ verts,
                                                      const float* __restrict__ weights,
                                                      float* __restrict__ out, int V,
                                                      SetupArgs sa) {
    __shared__ __align__(16) char smem[SMEM_TOTAL];

    int tid  = threadIdx.x;
    int lane = tid & 31;
    int warp = tid >> 5;
    int m4   = lane & 3;
    int grp  = lane >> 2;
    int v0   = blockIdx.x * NT;
    int nv   = min(NT, V - v0);

    // ================= phase 0: per-CTA setup =================
    {
        float (*sR)[NUM_J][12] = (float (*)[NUM_J][12])(smem);
        float (*sG)[NUM_J][12] = (float (*)[NUM_J][12])(smem + 17664);
        float (*sSh)[3]        = (float (*)[3])(smem + 35328);

        for (int i = tid; i < NP; i += THREADS) {
            sSh[i][0] = sa.rnd[i*3+0] + 3.0f * tanhf(sa.disp[i*3+0]);
            sSh[i][1] = sa.rnd[i*3+1] + 3.0f * tanhf(sa.disp[i*3+1]);
            sSh[i][2] = sa.rnd[i*3+2] + 3.0f * tanhf(sa.disp[i*3+2]);
        }
        for (int i = tid; i < NP * NUM_J; i += THREADS) {
            int p = i / NUM_J, j = i - p * NUM_J;
            float* R = sR[p][j];
            int s = c_slot[j];
            if (s < 0) {
                R[0]=1.f;R[1]=0.f;R[2]=0.f; R[3]=0.f;R[4]=1.f;R[5]=0.f; R[6]=0.f;R[7]=0.f;R[8]=1.f;
            } else {
                float sc = c_scale[s];
                float r0 = sc * tanhf(sa.prm[s][p*3+0]);
                float r1 = sc * tanhf(sa.prm[s][p*3+1]);
                float r2 = sc * tanhf(sa.prm[s][p*3+2]);
                float ang = sqrtf(r0*r0 + r1*r1 + r2*r2 + 1e-16f);
                float inv = 1.0f / ang;
                float ax = r0*inv, ay = r1*inv, az = r2*inv;
                float sn = sinf(ang), cs = cosf(ang), omc = 1.0f - cs;
                R[0] = cs + omc*ax*ax;      R[1] = omc*ax*ay - sn*az;  R[2] = omc*ax*az + sn*ay;
                R[3] = omc*ax*ay + sn*az;   R[4] = cs + omc*ay*ay;     R[5] = omc*ay*az - sn*ax;
                R[6] = omc*ax*az - sn*ay;   R[7] = omc*ay*az + sn*ax;  R[8] = cs + omc*az*az;
            }
            int par = c_parents[j];
            float rel0 = sa.joints[j*3+0], rel1 = sa.joints[j*3+1], rel2 = sa.joints[j*3+2];
            if (par >= 0) {
                rel0 -= sa.joints[par*3+0]; rel1 -= sa.joints[par*3+1]; rel2 -= sa.joints[par*3+2];
            }
            R[9] = rel0; R[10] = rel1; R[11] = rel2;
        }
        __syncthreads();

        // chain: 8 warps, poses {warp, warp+8}; lane m computes G element m
        {
            for (int wp = warp; wp < NP; wp += 8) {
#pragma unroll 1
                for (int jj = 0; jj < NUM_J; jj++) {
                    if (lane < 12) {
                        const float* Rj = sR[wp][jj];
                        float G;
                        if (jj == 0) {
                            G = Rj[lane];
                        } else {
                            const float* Gp = sG[wp][c_parents[jj]];
                            if (lane < 9) {
                                int r = lane / 3, c = lane - 3*(lane/3);
                                G = Gp[r*3+0]*Rj[c] + Gp[r*3+1]*Rj[3+c] + Gp[r*3+2]*Rj[6+c];
                            } else {
                                int r = lane - 9;
                                G = Gp[r*3+0]*Rj[9] + Gp[r*3+1]*Rj[10] + Gp[r*3+2]*Rj[11] + Gp[9+r];
                            }
                        }
                        sG[wp][jj][lane] = G;
                    }
                    __syncwarp();
                }
            }
        }
        __syncthreads();

        // CTA 0: posed joints output
        if (blockIdx.x == 0) {
            for (int i = tid; i < NP * NUM_J; i += THREADS) {
                int p = i / NUM_J, j = i - p * NUM_J;
                const float* G = sG[p][j];
                sa.outJ[i*3 + 0] = G[9]  + sSh[p][0];
                sa.outJ[i*3 + 1] = G[10] + sSh[p][1];
                sa.outJ[i*3 + 2] = G[11] + sSh[p][2];
            }
        }

        // frag emit: per-lane MMA A-fragments, written over dead sR region.
        // frag[((kb*3+mt)*2+side)*32 + lane] = {word(row,w0), word(row+8,w0),
        //                                       word(row,w0+4), word(row+8,w0+4)}
        // row = mt*16 + (lane>>2), w0 = kb*8 + (lane&3)
        // word(m,w): j=w>>1; w even -> {A[m][4j+0],A[m][4j+1]} = {G_i0,G_i1}
        //            w odd  -> {A[m][4j+2],A[m][4j+3]} = {G_i2, t_i}
        // t_i = G_t[i] - dot(G_row_i, jrest_j) + shift[p][i]
        uint4* fragSm = (uint4*)(smem + OFF_FRAG);
        for (int idx = tid; idx < 36 * 32; idx += THREADS) {
            int ln   = idx & 31;
            int rest = idx >> 5;
            int side = rest & 1;
            int mtkb = rest >> 1;
            int mt = mtkb % 3;
            int kb = mtkb / 3;
            int row = mt*16 + (ln >> 2);
            int w0  = kb*8 + (ln & 3);
            uint32_t wrd[4];
#pragma unroll
            for (int q = 0; q < 4; q++) {
                int m = row + (q & 1) * 8;
                int w = w0  + (q >> 1) * 4;
                int j = w >> 1;
                uint32_t res = 0;
                if (j < NUM_J) {
                    int p = m / 3, i = m - 3*p;
                    const float* G = sG[p][j];
                    float v0c, v1c;
                    if ((w & 1) == 0) {
                        v0c = G[i*3+0]; v1c = G[i*3+1];
                    } else {
                        v0c = G[i*3+2];
                        float jr0 = sa.joints[j*3+0], jr1 = sa.joints[j*3+1], jr2 = sa.joints[j*3+2];
                        v1c = G[9+i] - (G[i*3+0]*jr0 + G[i*3+1]*jr1 + G[i*3+2]*jr2) + sSh[p][i];
                    }
                    float h0, l0, h1, l1;
                    split_bf(v0c, h0, l0);
                    split_bf(v1c, h1, l1);
                    res = side ? pk2(l0, l1) : pk2(h0, h1);
                }
                wrd[q] = res;
            }
            fragSm[rest*32 + ln] = make_uint4(wrd[0], wrd[1], wrd[2], wrd[3]);
        }
    }
    __syncthreads();   // sG/sSh dead from here; staging may overwrite them

    // ================= phase 1: stage weights + verts =================
    float* sWf = (float*)(smem + OFF_W);
    float* sVf = (float*)(smem + OFF_V);
    {
        const float4* src = (const float4*)(weights + (size_t)v0 * NUM_J);
        int wn4 = (nv * NUM_J) >> 2;        // exact: nv*23 % 4 == 0 for nv in {192,32}
        for (int i = tid; i < (NT*NUM_J)/4; i += THREADS) {
            float4 f = make_float4(0.f, 0.f, 0.f, 0.f);
            if (i < wn4) f = __ldg(src + i);
            int e = 4*i;
            int v = e / NUM_J;
            int j = e - v*NUM_J;
            float vals[4] = {f.x, f.y, f.z, f.w};
#pragma unroll
            for (int k = 0; k < 4; k++) {
                sWf[v * W_STRIDE + j] = vals[k];
                if (++j == NUM_J) { j = 0; v++; }
            }
        }
        for (int v = tid; v < NT; v += THREADS) sWf[v * W_STRIDE + 23] = 0.f;
    }
    if (tid < NT) {
        sVf[tid*4 + 3] = 1.0f;
        if (tid >= nv) { sVf[tid*4+0] = 0.f; sVf[tid*4+1] = 0.f; sVf[tid*4+2] = 0.f; }
    }
    {
        int nf4 = (nv * 3) >> 2;            // exact for nv in {192, 32}
        if (tid < nf4) {
            float4 f = __ldg((const float4*)(verts + (size_t)v0*3) + tid);
            int e = tid * 4;
            sVf[(e/3)*4 + (e%3)] = f.x;
            sVf[((e+1)/3)*4 + ((e+1)%3)] = f.y;
            sVf[((e+2)/3)*4 + ((e+2)%3)] = f.z;
            sVf[((e+3)/3)*4 + ((e+3)%3)] = f.w;
        }
    }
    __syncthreads();

    // ================= phase 2: MMA =================
    float vc0[3], vc1[3];
    int woff[3];
#pragma unroll
    for (int t = 0; t < 3; t++) {
        int vB = (warp*3 + t)*8 + grp;
        float4 vq = *(const float4*)(sVf + vB*4);
        vc0[t] = (m4 & 1) ? vq.z : vq.x;
        vc1[t] = (m4 & 1) ? vq.w : vq.y;
        woff[t] = vB * W_STRIDE;
    }

    float d[3][3][4];
#pragma unroll
    for (int t = 0; t < 3; t++)
#pragma unroll
        for (int mt = 0; mt < 3; mt++)
#pragma unroll
            for (int q = 0; q < 4; q++) d[t][mt][q] = 0.f;

    int jbase = m4 >> 1;
    const uint4* frag = ((const uint4*)(smem + OFF_FRAG)) + lane;

#pragma unroll
    for (int kb = 0; kb < 6; kb++) {
        int jl = 4*kb + jbase;               // jl+2 <= 23 (padded zero col)
        uint32_t bh[3][2], bl[3][2];
#pragma unroll
        for (int t = 0; t < 3; t++) {
            float wl = sWf[woff[t] + jl];
            float wh = sWf[woff[t] + jl + 2];
            float p0 = wl*vc0[t], p1 = wl*vc1[t], p2 = wh*vc0[t], p3 = wh*vc1[t];
            bh[t][0] = prmt_hi(p0, p1);
            bh[t][1] = prmt_hi(p2, p3);
            float l0 = p0 - trunc_hi(p0);
            float l1 = p1 - trunc_hi(p1);
            float l2 = p2 - trunc_hi(p2);
            float l3 = p3 - trunc_hi(p3);
            bl[t][0] = prmt_hi(l0, l1);
            bl[t][1] = prmt_hi(l2, l3);
        }
#pragma unroll
        for (int mt = 0; mt < 3; mt++) {
            uint4 ah = frag[((kb*3 + mt)*2 + 0)*32];
            mma16816(d[0][mt], ah.x, ah.y, ah.z, ah.w, bh[0][0], bh[0][1]);
            mma16816(d[1][mt], ah.x, ah.y, ah.z, ah.w, bh[1][0], bh[1][1]);
            mma16816(d[2][mt], ah.x, ah.y, ah.z, ah.w, bh[2][0], bh[2][1]);
            mma16816(d[0][mt], ah.x, ah.y, ah.z, ah.w, bl[0][0], bl[0][1]);
            mma16816(d[1][mt], ah.x, ah.y, ah.z, ah.w, bl[1][0], bl[1][1]);
            mma16816(d[2][mt], ah.x, ah.y, ah.z, ah.w, bl[2][0], bl[2][1]);
            uint4 al = frag[((kb*3 + mt)*2 + 1)*32];
            mma16816(d[0][mt], al.x, al.y, al.z, al.w, bh[0][0], bh[0][1]);
            mma16816(d[1][mt], al.x, al.y, al.z, al.w, bh[1][0], bh[1][1]);
            mma16816(d[2][mt], al.x, al.y, al.z, al.w, bh[2][0], bh[2][1]);
        }
    }
    __syncthreads();

    // ================= phase 3: epilogue =================
    float* sE = (float*)smem;
#pragma unroll
    for (int t = 0; t < 3; t++) {
        int vb = (warp*3 + t)*8 + 2*m4;
#pragma unroll
        for (int mt = 0; mt < 3; mt++) {
            int r0 = mt*16 + grp;
            int r1 = r0 + 8;
            int pA = r0/3, iA = r0 - 3*pA;
            int pB = r1/3, iB = r1 - 3*pB;
            sE[pA*POSE_STRIDE + vb*3     + iA] = d[t][mt][0];
            sE[pA*POSE_STRIDE + (vb+1)*3 + iA] = d[t][mt][1];
            sE[pB*POSE_STRIDE + vb*3     + iB] = d[t][mt][2];
            sE[pB*POSE_STRIDE + (vb+1)*3 + iB] = d[t][mt][3];
        }
    }
    __syncthreads();

    size_t V3 = (size_t)V * 3;
    int nf4 = (nv * 3) >> 2;                   // valid float4 per pose (144 or 24)
    for (int q = tid; q < NP * 144; q += THREADS) {
        int p = q / 144, r = q - p*144;
        if (r < nf4) {
            float4 val = *(const float4*)(sE + p*POSE_STRIDE + r*4);
            *(float4*)(out + (size_t)p*V3 + (size_t)v0*3 + r*4) = val;
        }
    }
}

// ---------------------------------------------------------------------------
extern "C" void kernel_launch(void* const* d_in, const int* in_sizes, int n_in,
                              void* d_out, int out_size) {
    const float* vertices = (const float*)d_in[0];   // (1,V,3)
    const float* joints   = (const float*)d_in[1];   // (1,23,3)
    const float* weights  = (const float*)d_in[2];   // (V,23)
    const float* disp     = (const float*)d_in[3];   // (16,1,3)
    const float* rnd      = (const float*)d_in[4];   // (16,3)

    int V = in_sizes[0] / 3;
    float* out = (float*)d_out;

    SetupArgs sa;
    sa.joints = joints;
    sa.disp   = disp;
    sa.rnd    = rnd;
    for (int i = 0; i < 11; i++) sa.prm[i] = (const float*)d_in[5 + i];
    sa.outJ = out + (size_t)NP * V * 3;

    int blocks = (V + NT - 1) / NT;
    lbs_one<<<blocks, THREADS>>>(vertices, weights, out, V, sa);
}

// round 17
// speedup vs baseline: 2.1927x; 2.1927x over previous
#include <cuda_runtime.h>
#include <cuda_bf16.h>
#include <math.h>
#include <stdint.h>

#define NUM_J 23
#define NP 16
#define NT 192                 // vertices per CTA tile (8 warps x 3 n8-tiles x 8)
#define THREADS 256
#define W_STRIDE 24            // padded weights row (col 23 = 0)

#define OFF_W  0                              // float [192][24] = 18432 B
#define OFF_V  (NT*W_STRIDE*4)                // 18432: float4 [192] = 3072 B
#define POSE_STRIDE 580                       // floats per pose in epilogue (192*3+4)
#define SMEM_TOTAL (NP*POSE_STRIDE*4)         // 37120 B (epilogue aliases staging)

// Pre-swizzled per-lane MMA A-fragments: [(kb*3+mt)*2+side][lane] -> 4 u32.
// j=23 pad words never written -> stay zero (static zero-init).
__device__ uint4 g_Afrag[6 * 3 * 2 * 32];

// ---------------- helpers ----------------
__device__ __forceinline__ uint32_t pk2(float lo, float hi) {
    __nv_bfloat162 t = __floats2bfloat162_rn(lo, hi);
    return *reinterpret_cast<uint32_t*>(&t);
}
__device__ __forceinline__ void split_bf(float v, float& h, float& l) {
    h = __bfloat162float(__float2bfloat16_rn(v));
    l = v - h;
}
__device__ __forceinline__ uint32_t prmt_hi(float a, float b) {   // {hi16(a), hi16(b)}
    uint32_t r;
    asm("prmt.b32 %0, %1, %2, 0x7632;" : "=r"(r)
        : "r"(__float_as_uint(a)), "r"(__float_as_uint(b)));
    return r;
}
__device__ __forceinline__ float trunc_hi(float a) {
    return __uint_as_float(__float_as_uint(a) & 0xffff0000u);
}
__device__ __forceinline__ void mma16816(float (&d)[4],
                                         uint32_t a0, uint32_t a1, uint32_t a2, uint32_t a3,
                                         uint32_t b0, uint32_t b1) {
    asm volatile("mma.sync.aligned.m16n8k16.row.col.f32.bf16.bf16.f32 "
                 "{%0,%1,%2,%3}, {%4,%5,%6,%7}, {%8,%9}, {%0,%1,%2,%3};"
                 : "+f"(d[0]), "+f"(d[1]), "+f"(d[2]), "+f"(d[3])
                 : "r"(a0), "r"(a1), "r"(a2), "r"(a3), "r"(b0), "r"(b1));
}

struct SetupArgs {
    const float* joints;
    const float* disp;
    const float* rnd;
    const float* prm[11];
    float* outJ;
};

__device__ const int   c_parents[NUM_J] = {-1,0,1,1,3,4,5,4,7,4,9,1,11,12,13,12,15,12,17,0,19,0,21};
__device__ const int   c_slot[NUM_J]    = { 0,-1,-1,1,2,3,-1,4,-1,5,-1,6,7,8,-1,9,-1,10,-1,-1,-1,-1,-1};
__device__ const float c_scale[11]      = {0.7853981633974483f, 1.5707963267948966f, 1.5707963267948966f,
                                           0.7853981633974483f, 0.7853981633974483f, 0.7853981633974483f,
                                           1.5707963267948966f, 1.5707963267948966f, 0.7853981633974483f,
                                           0.7853981633974483f, 0.7853981633974483f};

// ---------------------------------------------------------------------------
// Kernel 1: setup — 16 CTAs (one per pose) x 64 threads.
//  - Rodrigues for this pose's 23 joints in parallel
//  - 23-step kinematic chain on warp 0 (lane m = G element m)
//  - posed-joints output for this pose
//  - scatter this pose's 288 frag words (32-bit components of g_Afrag;
//    rows m=3p..3p+2 are disjoint across poses -> race-free)
// ---------------------------------------------------------------------------
__global__ void lbs_setup(SetupArgs a) {
    __shared__ float sR[NUM_J][12];
    __shared__ float sG[NUM_J][12];
    __shared__ float sSh[3];

    int p = blockIdx.x;            // pose
    int t = threadIdx.x;

    if (t == 0) {
        sSh[0] = a.rnd[p*3+0] + 3.0f * tanhf(a.disp[p*3+0]);
        sSh[1] = a.rnd[p*3+1] + 3.0f * tanhf(a.disp[p*3+1]);
        sSh[2] = a.rnd[p*3+2] + 3.0f * tanhf(a.disp[p*3+2]);
    }
    if (t >= 32 && t < 32 + NUM_J) {
        int j = t - 32;
        float* R = sR[j];
        int s = c_slot[j];
        if (s < 0) {
            R[0]=1.f;R[1]=0.f;R[2]=0.f; R[3]=0.f;R[4]=1.f;R[5]=0.f; R[6]=0.f;R[7]=0.f;R[8]=1.f;
        } else {
            float sc = c_scale[s];
            float r0 = sc * tanhf(a.prm[s][p*3+0]);
            float r1 = sc * tanhf(a.prm[s][p*3+1]);
            float r2 = sc * tanhf(a.prm[s][p*3+2]);
            float ang = sqrtf(r0*r0 + r1*r1 + r2*r2 + 1e-16f);
            float inv = 1.0f / ang;
            float ax = r0*inv, ay = r1*inv, az = r2*inv;
            float sn = sinf(ang), cs = cosf(ang), omc = 1.0f - cs;
            R[0] = cs + omc*ax*ax;      R[1] = omc*ax*ay - sn*az;  R[2] = omc*ax*az + sn*ay;
            R[3] = omc*ax*ay + sn*az;   R[4] = cs + omc*ay*ay;     R[5] = omc*ay*az - sn*ax;
            R[6] = omc*ax*az - sn*ay;   R[7] = omc*ay*az + sn*ax;  R[8] = cs + omc*az*az;
        }
        int par = c_parents[j];
        float rel0 = a.joints[j*3+0], rel1 = a.joints[j*3+1], rel2 = a.joints[j*3+2];
        if (par >= 0) { rel0 -= a.joints[par*3+0]; rel1 -= a.joints[par*3+1]; rel2 -= a.joints[par*3+2]; }
        R[9] = rel0; R[10] = rel1; R[11] = rel2;
    }
    __syncthreads();

    // chain on warp 0: 23 steps, lane m computes element m
    if (t < 32) {
#pragma unroll 1
        for (int jj = 0; jj < NUM_J; jj++) {
            if (t < 12) {
                const float* Rj = sR[jj];
                float G;
                if (jj == 0) {
                    G = Rj[t];
                } else {
                    const float* Gp = sG[c_parents[jj]];
                    if (t < 9) {
                        int r = t / 3, c = t - 3*(t/3);
                        G = Gp[r*3+0]*Rj[c] + Gp[r*3+1]*Rj[3+c] + Gp[r*3+2]*Rj[6+c];
                    } else {
                        int r = t - 9;
                        G = Gp[r*3+0]*Rj[9] + Gp[r*3+1]*Rj[10] + Gp[r*3+2]*Rj[11] + Gp[9+r];
                    }
                }
                sG[jj][t] = G;
            }
            __syncwarp();
        }
    }
    __syncthreads();

    // posed joints out for this pose
    if (t < NUM_J) {
        const float* G = sG[t];
        a.outJ[(p*NUM_J + t)*3 + 0] = G[9]  + sSh[0];
        a.outJ[(p*NUM_J + t)*3 + 1] = G[10] + sSh[1];
        a.outJ[(p*NUM_J + t)*3 + 2] = G[11] + sSh[2];
    }

    // frag word scatter for rows m = 3p+i.
    // word(m, w): j = w>>1; w even -> {G_i0, G_i1}; w odd -> {G_i2, t_i},
    //   t_i = G_t[i] - dot(G_row_i, jrest_j) + shift_i      (shift folded;
    //   valid because weight rows sum to 1)
    // frag uint4 at [rest][ln]: components q: (row+8*(q&1), w0+4*(q>>1)),
    //   rest = (kb*3+mt)*2+side, row = mt*16 + (ln>>2), w0 = kb*8 + (ln&3)
    // For m: mt = m/16, lr = m%16; qbit = lr>=8; lgrp = lr%8.
    uint32_t* fragW = (uint32_t*)g_Afrag;
    for (int idx = t; idx < 3 * 6 * 4 * 2 * 2; idx += blockDim.x) {
        int rem   = idx;
        int side  = rem & 1;  rem >>= 1;
        int whalf = rem & 1;  rem >>= 1;
        int lnlow = rem & 3;  rem >>= 2;
        int kb    = rem % 6;
        int i     = rem / 6;

        int m  = 3*p + i;
        int mt = m >> 4;
        int lr = m & 15;
        int qbit = lr >> 3;
        int lgrp = lr & 7;

        int w = kb*8 + lnlow + whalf*4;
        int j = w >> 1;
        uint32_t res = 0;
        if (j < NUM_J) {
            const float* G = sG[j];
            float v0c, v1c;
            if ((w & 1) == 0) {
                v0c = G[i*3+0]; v1c = G[i*3+1];
            } else {
                v0c = G[i*3+2];
                float jr0 = a.joints[j*3+0], jr1 = a.joints[j*3+1], jr2 = a.joints[j*3+2];
                v1c = G[9+i] - (G[i*3+0]*jr0 + G[i*3+1]*jr1 + G[i*3+2]*jr2) + sSh[i];
            }
            float h0, l0, h1, l1;
            split_bf(v0c, h0, l0);
            split_bf(v1c, h1, l1);
            res = side ? pk2(l0, l1) : pk2(h0, h1);
        }
        int rest = (kb*3 + mt)*2 + side;
        int ln   = lgrp*4 + lnlow;
        int q    = qbit + whalf*2;
        fragW[(rest*32 + ln)*4 + q] = res;
    }
}

// ---------------------------------------------------------------------------
// Kernel 2 (byte-identical to the 71.3us best): 192-vertex tile GEMM via
// mma.sync (bf16 hi/lo, 3 passes). A fragments via hot-L1 LDG.128 (g_Afrag);
// B built with truncation-split (PRMT/LOP/FADD only).
// ---------------------------------------------------------------------------
__global__ __launch_bounds__(THREADS, 3) void lbs_mma(const float* __restrict__ verts,
                                                      const float* __restrict__ weights,
                                                      float* __restrict__ out, int V) {
    __shared__ __align__(16) char smem[SMEM_TOTAL];
    float* sWf = (float*)(smem + OFF_W);
    float* sVf = (float*)(smem + OFF_V);

    int tid  = threadIdx.x;
    int lane = tid & 31;
    int warp = tid >> 5;
    int m4   = lane & 3;
    int grp  = lane >> 2;
    int v0   = blockIdx.x * NT;
    int nv   = min(NT, V - v0);

    // ---- stage weights: float4 loads -> padded [NT][24] smem, col 23 = 0 ----
    {
        const float4* src = (const float4*)(weights + (size_t)v0 * NUM_J);
        int wn4 = (nv * NUM_J) >> 2;        // exact: nv*23 % 4 == 0 for nv in {192,32}
        for (int i = tid; i < (NT*NUM_J)/4; i += THREADS) {
            float4 f = make_float4(0.f, 0.f, 0.f, 0.f);
            if (i < wn4) f = __ldg(src + i);
            int e = 4*i;
            int v = e / NUM_J;
            int j = e - v*NUM_J;
            float vals[4] = {f.x, f.y, f.z, f.w};
#pragma unroll
            for (int k = 0; k < 4; k++) {
                sWf[v * W_STRIDE + j] = vals[k];
                if (++j == NUM_J) { j = 0; v++; }
            }
        }
        for (int v = tid; v < NT; v += THREADS) sWf[v * W_STRIDE + 23] = 0.f;
    }
    // ---- stage verts as (x,y,z,1), zeros beyond nv ----
    if (tid < NT) {
        sVf[tid*4 + 3] = 1.0f;
        if (tid >= nv) { sVf[tid*4+0] = 0.f; sVf[tid*4+1] = 0.f; sVf[tid*4+2] = 0.f; }
    }
    {
        int nf4 = (nv * 3) >> 2;            // exact for nv in {192, 32}
        if (tid < nf4) {
            float4 f = __ldg((const float4*)(verts + (size_t)v0*3) + tid);
            int e = tid * 4;
            sVf[(e/3)*4 + (e%3)] = f.x;
            sVf[((e+1)/3)*4 + ((e+1)%3)] = f.y;
            sVf[((e+2)/3)*4 + ((e+2)%3)] = f.z;
            sVf[((e+3)/3)*4 + ((e+3)%3)] = f.w;
        }
    }
    __syncthreads();

    // per-tile preload: vertex components + padded weight row offsets
    float vc0[3], vc1[3];
    int woff[3];
#pragma unroll
    for (int t = 0; t < 3; t++) {
        int vB = (warp*3 + t)*8 + grp;
        float4 vq = *(const float4*)(sVf + vB*4);
        vc0[t] = (m4 & 1) ? vq.z : vq.x;
        vc1[t] = (m4 & 1) ? vq.w : vq.y;
        woff[t] = vB * W_STRIDE;
    }

    float d[3][3][4];
#pragma unroll
    for (int t = 0; t < 3; t++)
#pragma unroll
        for (int mt = 0; mt < 3; mt++)
#pragma unroll
            for (int q = 0; q < 4; q++) d[t][mt][q] = 0.f;

    int jbase = m4 >> 1;
    const uint4* frag = g_Afrag + lane;

#pragma unroll
    for (int kb = 0; kb < 6; kb++) {
        int jl = 4*kb + jbase;               // jl+2 <= 23 (padded zero col)
        uint32_t bh[3][2], bl[3][2];
#pragma unroll
        for (int t = 0; t < 3; t++) {
            float wl = sWf[woff[t] + jl];
            float wh = sWf[woff[t] + jl + 2];
            float p0 = wl*vc0[t], p1 = wl*vc1[t], p2 = wh*vc0[t], p3 = wh*vc1[t];
            bh[t][0] = prmt_hi(p0, p1);
            bh[t][1] = prmt_hi(p2, p3);
            float l0 = p0 - trunc_hi(p0);
            float l1 = p1 - trunc_hi(p1);
            float l2 = p2 - trunc_hi(p2);
            float l3 = p3 - trunc_hi(p3);
            bl[t][0] = prmt_hi(l0, l1);
            bl[t][1] = prmt_hi(l2, l3);
        }
#pragma unroll
        for (int mt = 0; mt < 3; mt++) {
            uint4 ah = __ldg(frag + ((kb*3 + mt)*2 + 0)*32);
            mma16816(d[0][mt], ah.x, ah.y, ah.z, ah.w, bh[0][0], bh[0][1]);
            mma16816(d[1][mt], ah.x, ah.y, ah.z, ah.w, bh[1][0], bh[1][1]);
            mma16816(d[2][mt], ah.x, ah.y, ah.z, ah.w, bh[2][0], bh[2][1]);
            mma16816(d[0][mt], ah.x, ah.y, ah.z, ah.w, bl[0][0], bl[0][1]);
            mma16816(d[1][mt], ah.x, ah.y, ah.z, ah.w, bl[1][0], bl[1][1]);
            mma16816(d[2][mt], ah.x, ah.y, ah.z, ah.w, bl[2][0], bl[2][1]);
            uint4 al = __ldg(frag + ((kb*3 + mt)*2 + 1)*32);
            mma16816(d[0][mt], al.x, al.y, al.z, al.w, bh[0][0], bh[0][1]);
            mma16816(d[1][mt], al.x, al.y, al.z, al.w, bh[1][0], bh[1][1]);
            mma16816(d[2][mt], al.x, al.y, al.z, al.w, bh[2][0], bh[2][1]);
        }
    }
    __syncthreads();

    // ---- epilogue: D -> smem in output layout [pose][v*3+i] ----
    float* sE = (float*)smem;
#pragma unroll
    for (int t = 0; t < 3; t++) {
        int vb = (warp*3 + t)*8 + 2*m4;
#pragma unroll
        for (int mt = 0; mt < 3; mt++) {
            int r0 = mt*16 + grp;
            int r1 = r0 + 8;
            int pA = r0/3, iA = r0 - 3*pA;
            int pB = r1/3, iB = r1 - 3*pB;
            sE[pA*POSE_STRIDE + vb*3     + iA] = d[t][mt][0];
            sE[pA*POSE_STRIDE + (vb+1)*3 + iA] = d[t][mt][1];
            sE[pB*POSE_STRIDE + vb*3     + iB] = d[t][mt][2];
            sE[pB*POSE_STRIDE + (vb+1)*3 + iB] = d[t][mt][3];
        }
    }
    __syncthreads();

    // ---- coalesced float4 copy out ----
    size_t V3 = (size_t)V * 3;
    int nf4 = (nv * 3) >> 2;                   // valid float4 per pose (144 or 24)
    for (int q = tid; q < NP * 144; q += THREADS) {
        int p = q / 144, r = q - p*144;
        if (r < nf4) {
            float4 val = *(const float4*)(sE + p*POSE_STRIDE + r*4);
            *(float4*)(out + (size_t)p*V3 + (size_t)v0*3 + r*4) = val;
        }
    }
}

// ---------------------------------------------------------------------------
extern "C" void kernel_launch(void* const* d_in, const int* in_sizes, int n_in,
                              void* d_out, int out_size) {
    const float* vertices = (const float*)d_in[0];   // (1,V,3)
    const float* joints   = (const float*)d_in[1];   // (1,23,3)
    const float* weights  = (const float*)d_in[2];   // (V,23)
    const float* disp     = (const float*)d_in[3];   // (16,1,3)
    const float* rnd      = (const float*)d_in[4];   // (16,3)

    int V = in_sizes[0] / 3;
    float* out = (float*)d_out;

    SetupArgs sa;
    sa.joints = joints;
    sa.disp   = disp;
    sa.rnd    = rnd;
    for (int i = 0; i < 11; i++) sa.prm[i] = (const float*)d_in[5 + i];
    sa.outJ = out + (size_t)NP * V * 3;

    lbs_setup<<<NP, 64>>>(sa);
    int blocks = (V + NT - 1) / NT;
    lbs_mma<<<blocks, THREADS>>>(vertices, weights, out, V);
}